// round 14
// baseline (speedup 1.0000x reference)
#include <cuda_runtime.h>
#include <cuda_bf16.h>
#include <cstdint>
#include <math.h>

#define B_   16
#define C_   256
#define H_   32
#define W_   32
#define HW   1024
#define HM   128
#define WM   128
#define HWM  16384
#define N_   100
#define F_   1024
#define NH_  8
#define HD   32
#define L_   2
#define EPSF 1e-5f

#define OUT_Q     0
#define OUT_PRED  (B_*N_*C_)
#define OUT_INTER (OUT_PRED + B_*N_*HWM)

#define OFF_Q    0L
#define OFF_E1   409600L
#define OFF_E    819200L
#define OFF_QB   1228800L
#define OFF_OB   1638400L
#define OFF_TMP  2048000L
#define OFF_FFH  2457600L
#define OFF_FE   4096000L
#define OFF_KB   8290304L
#define OFF_VB   12484608L
#define SCRATCH_FLOATS (12484608L + 4194304L)

__device__ float g_scratch[SCRATCH_FLOATS];
__device__ unsigned char g_am[B_ * N_ * HW];

__device__ __forceinline__ uint32_t smem_u32(const void* p) {
    uint32_t a;
    asm("{ .reg .u64 t; cvta.to.shared.u64 t, %1; cvt.u32.u64 %0, t; }" : "=r"(a) : "l"(p));
    return a;
}

__device__ __forceinline__ void ldsm_x4(uint32_t r[4], uint32_t addr) {
    asm volatile("ldmatrix.sync.aligned.m8n8.x4.shared.b16 {%0,%1,%2,%3}, [%4];"
                 : "=r"(r[0]), "=r"(r[1]), "=r"(r[2]), "=r"(r[3]) : "r"(addr));
}

__device__ __forceinline__ void mma_bf16(float c[4], const uint32_t a[4],
                                         uint32_t b0, uint32_t b1) {
    asm volatile(
        "mma.sync.aligned.m16n8k16.row.col.f32.bf16.bf16.f32 "
        "{%0,%1,%2,%3}, {%4,%5,%6,%7}, {%8,%9}, {%0,%1,%2,%3};"
        : "+f"(c[0]), "+f"(c[1]), "+f"(c[2]), "+f"(c[3])
        : "r"(a[0]), "r"(a[1]), "r"(a[2]), "r"(a[3]), "r"(b0), "r"(b1));
}

__device__ __forceinline__ void bf_split_pair(float x0, float x1, uint32_t& hp, uint32_t& lp) {
    __nv_bfloat16 h0 = __float2bfloat16(x0);
    __nv_bfloat16 h1 = __float2bfloat16(x1);
    __nv_bfloat16 l0 = __float2bfloat16(x0 - __bfloat162float(h0));
    __nv_bfloat16 l1 = __float2bfloat16(x1 - __bfloat162float(h1));
    hp = (uint32_t)__bfloat16_as_ushort(h0) | ((uint32_t)__bfloat16_as_ushort(h1) << 16);
    lp = (uint32_t)__bfloat16_as_ushort(l0) | ((uint32_t)__bfloat16_as_ushort(l1) << 16);
}

// ============================================================
// gemm_bf v4: bf16 3-split GEMM, mma.m16n8k16 + ldmatrix.
// Tile 64(M) x 64(N), BK=32; 128 thr / 4 warps (2x2), warp tile 32x32.
// Sized for 4 CTAs/SM (__launch_bounds__(128,4), smem 20.5KB/CTA).
// A [M,K] f32 rm, B [K,N] f32 rm, C = A·B (+bias)(relu).
// N%64==0, K%32==0, M guarded. PAD=40 rows -> conflict-free ldmatrix.
// ============================================================
#define PAD 40
__global__ void __launch_bounds__(128, 4)
gemm_bf(const float* __restrict__ A, const float* __restrict__ B,
        const float* __restrict__ bias, float* __restrict__ C,
        int M, int N, int K, int relu, long sA, long sB, long sC)
{
    __shared__ __nv_bfloat16 AH[64 * PAD], AL[64 * PAD];
    __shared__ __nv_bfloat16 BH[64 * PAD], BL[64 * PAD];

    A += blockIdx.z * sA;  B += blockIdx.z * sB;  C += blockIdx.z * sC;

    int tid = threadIdx.x, w = tid >> 5, lane = tid & 31;
    int m0 = blockIdx.y * 64, n0 = blockIdx.x * 64;
    int wm = (w & 1) * 32, wn = (w >> 1) * 32;
    int lr = lane >> 2, lc = lane & 3;

    uint32_t ah_b = smem_u32(AH), al_b = smem_u32(AL);
    uint32_t bh_b = smem_u32(BH), bl_b = smem_u32(BL);

    // loader indices
    int ar  = tid >> 1, aks = (tid & 1) * 16;       // A: row 0..63, k-half
    bool aok = (m0 + ar) < M;
    int bn  = tid & 63, bkh = (tid >> 6) * 16;      // B: col 0..63, k-half

    float acc[2][4][4];
#pragma unroll
    for (int mt = 0; mt < 2; mt++)
#pragma unroll
        for (int nt = 0; nt < 4; nt++)
#pragma unroll
            for (int i = 0; i < 4; i++) acc[mt][nt][i] = 0.f;

    float fa[16], fb[16];

    auto load_chunk = [&](int k0) {
        if (aok) {
            const float4* ap = (const float4*)(A + (long)(m0 + ar) * K + k0 + aks);
#pragma unroll
            for (int q = 0; q < 4; q++) { float4 v = ap[q];
                fa[q*4]=v.x; fa[q*4+1]=v.y; fa[q*4+2]=v.z; fa[q*4+3]=v.w; }
        } else {
#pragma unroll
            for (int q = 0; q < 16; q++) fa[q] = 0.f;
        }
#pragma unroll
        for (int j = 0; j < 16; j++)
            fb[j] = B[(long)(k0 + bkh + j) * N + n0 + bn];
    };

    auto store_chunk = [&]() {
        uint32_t hw[8], lw[8];
#pragma unroll
        for (int j = 0; j < 8; j++) bf_split_pair(fa[2*j], fa[2*j+1], hw[j], lw[j]);
        uint32_t* dst = (uint32_t*)&AH[ar * PAD + aks];
        *(uint4*)(dst)     = make_uint4(hw[0], hw[1], hw[2], hw[3]);
        *(uint4*)(dst + 4) = make_uint4(hw[4], hw[5], hw[6], hw[7]);
        dst = (uint32_t*)&AL[ar * PAD + aks];
        *(uint4*)(dst)     = make_uint4(lw[0], lw[1], lw[2], lw[3]);
        *(uint4*)(dst + 4) = make_uint4(lw[4], lw[5], lw[6], lw[7]);
#pragma unroll
        for (int j = 0; j < 8; j++) bf_split_pair(fb[2*j], fb[2*j+1], hw[j], lw[j]);
        dst = (uint32_t*)&BH[bn * PAD + bkh];
        *(uint4*)(dst)     = make_uint4(hw[0], hw[1], hw[2], hw[3]);
        *(uint4*)(dst + 4) = make_uint4(hw[4], hw[5], hw[6], hw[7]);
        dst = (uint32_t*)&BL[bn * PAD + bkh];
        *(uint4*)(dst)     = make_uint4(lw[0], lw[1], lw[2], lw[3]);
        *(uint4*)(dst + 4) = make_uint4(lw[4], lw[5], lw[6], lw[7]);
    };

    int NCH = K / 32;
    load_chunk(0);

    for (int t = 0; t < NCH; t++) {
        store_chunk();
        __syncthreads();
        if (t + 1 < NCH) load_chunk((t + 1) * 32);   // gmem loads overlap MMA

#pragma unroll
        for (int ks = 0; ks < 32; ks += 16) {
            uint32_t aH[2][4], aL[2][4];
#pragma unroll
            for (int mt = 0; mt < 2; mt++) {
                uint32_t off = (uint32_t)((wm + mt*16 + (lane & 15)) * PAD
                                          + ks + ((lane >> 4) << 3)) * 2;
                ldsm_x4(aH[mt], ah_b + off);
                ldsm_x4(aL[mt], al_b + off);
            }
#pragma unroll
            for (int dt = 0; dt < 2; dt++) {
                uint32_t bh[4], bl[4];
                uint32_t off = (uint32_t)((wn + dt*16 + ((lane >> 4) << 3) + (lane & 7)) * PAD
                                          + ks + (((lane >> 3) & 1) << 3)) * 2;
                ldsm_x4(bh, bh_b + off);
                ldsm_x4(bl, bl_b + off);
#pragma unroll
                for (int s = 0; s < 2; s++) {
                    int nt = dt * 2 + s;
                    uint32_t b0h = bh[2*s], b1h = bh[2*s+1];
                    uint32_t b0l = bl[2*s], b1l = bl[2*s+1];
#pragma unroll
                    for (int mt = 0; mt < 2; mt++) {
                        mma_bf16(acc[mt][nt], aH[mt], b0h, b1h);
                        mma_bf16(acc[mt][nt], aH[mt], b0l, b1l);
                        mma_bf16(acc[mt][nt], aL[mt], b0h, b1h);
                    }
                }
            }
        }
        __syncthreads();
    }

    // epilogue (validated fragment addressing)
#pragma unroll
    for (int mt = 0; mt < 2; mt++) {
#pragma unroll
        for (int nt = 0; nt < 4; nt++) {
            int row = m0 + wm + mt * 16 + lr;
            int col = n0 + wn + nt * 8 + lc * 2;
            float bx = 0.f, by = 0.f;
            if (bias) { bx = bias[col]; by = bias[col + 1]; }
            float2 v0, v1;
            v0.x = acc[mt][nt][0] + bx; v0.y = acc[mt][nt][1] + by;
            v1.x = acc[mt][nt][2] + bx; v1.y = acc[mt][nt][3] + by;
            if (relu) {
                v0.x = fmaxf(v0.x, 0.f); v0.y = fmaxf(v0.y, 0.f);
                v1.x = fmaxf(v1.x, 0.f); v1.y = fmaxf(v1.y, 0.f);
            }
            if (row < M)     *(float2*)(C + (long)row * N + col)       = v0;
            if (row + 8 < M) *(float2*)(C + (long)(row + 8) * N + col) = v1;
        }
    }
}

// ============================================================
// feats transpose: (B, C, HW) -> (B, HW, C)
// ============================================================
__global__ void feats_transpose(const float* __restrict__ feat, float* __restrict__ out)
{
    __shared__ float tile[32][33];
    int b  = blockIdx.z;
    int c0 = blockIdx.x * 32;
    int s0 = blockIdx.y * 32;
    int tx = threadIdx.x, ty = threadIdx.y;
#pragma unroll
    for (int i = 0; i < 32; i += 8)
        tile[ty + i][tx] = feat[((long)b * C_ + c0 + ty + i) * HW + s0 + tx];
    __syncthreads();
#pragma unroll
    for (int i = 0; i < 32; i += 8)
        out[((long)b * HW + s0 + ty + i) * C_ + c0 + tx] = tile[tx][ty + i];
}

__global__ void bcast_queries(const float* __restrict__ qe, float* __restrict__ q)
{
    int i = blockIdx.x * blockDim.x + threadIdx.x;
    if (i < B_ * N_ * C_) q[i] = qe[i % (N_ * C_)];
}

// ============================================================
// attention mask from cur
// ============================================================
__global__ void mask_kernel(const float* __restrict__ cur, unsigned char* __restrict__ am)
{
    int row = blockIdx.x;
    int t = threadIdx.x;
    int y = t >> 5, x = t & 31;
    const float* p = cur + (long)row * HWM;
    int r0 = 4 * y + 1, c0 = 4 * x + 1;
    float v00 = p[r0 * WM + c0],       v01 = p[r0 * WM + c0 + 1];
    float v10 = p[(r0 + 1) * WM + c0], v11 = p[(r0 + 1) * WM + c0 + 1];
    float s = 1.f / (1.f + expf(-v00)) + 1.f / (1.f + expf(-v01))
            + 1.f / (1.f + expf(-v10)) + 1.f / (1.f + expf(-v11));
    int m = (0.25f * s) > 0.5f;

    __shared__ int cnt[32];
    unsigned bal = __ballot_sync(0xffffffffu, m);
    if ((t & 31) == 0) cnt[t >> 5] = __popc(bal);
    __syncthreads();
    if (t < 32) {
        int v = cnt[t];
#pragma unroll
        for (int o = 16; o > 0; o >>= 1) v += __shfl_down_sync(0xffffffffu, v, o);
        if (t == 0) cnt[0] = v;
    }
    __syncthreads();
    am[(long)row * HW + t] = (cnt[0] == 0) ? (unsigned char)1 : (unsigned char)m;
}

// ============================================================
// attention v2 (dynamic smem): block per (h, b); flash-style.
// ============================================================
struct AttnSmem {
    float Ks[128][36];
    float Vs[128][36];
    float qsm[N_][32];
    float psm[8][4][128];
};

extern __shared__ char attn_smem_raw[];

__global__ void __launch_bounds__(256)
attn2(const float* __restrict__ Q, const float* __restrict__ K,
      const float* __restrict__ V, const unsigned char* __restrict__ am,
      float* __restrict__ O)
{
    AttnSmem& sm = *reinterpret_cast<AttnSmem*>(attn_smem_raw);
    int h = blockIdx.x, b = blockIdx.y;

    int tid = threadIdx.x, w = tid >> 5, lane = tid & 31;

    for (int n = w; n < N_; n += 8)
        sm.qsm[n][lane] = Q[((long)(b * N_ + n)) * C_ + h * HD + lane];

    float m[4][4], su[4][4], oa[4][4];
#pragma unroll
    for (int t = 0; t < 4; t++)
#pragma unroll
        for (int qq = 0; qq < 4; qq++) { m[t][qq] = -1e30f; su[t][qq] = 0.f; oa[t][qq] = 0.f; }

    const unsigned char* amb = am + (long)b * N_ * HW;
    const float scale = 0.17677669529663687f;

    for (int c0 = 0; c0 < HW; c0 += 128) {
        __syncthreads();
#pragma unroll
        for (int it = 0; it < 4; it++) {
            int i = tid + it * 256;
            int r = i >> 3, d4 = (i & 7) * 4;
            float4 kv = *(const float4*)(K + ((long)(b * HW + c0 + r)) * C_ + h * HD + d4);
            *(float4*)&sm.Ks[r][d4] = kv;
            float4 vv = *(const float4*)(V + ((long)(b * HW + c0 + r)) * C_ + h * HD + d4);
            *(float4*)&sm.Vs[r][d4] = vv;
        }
        __syncthreads();

#pragma unroll
        for (int t = 0; t < 4; t++) {
            int g = w + 8 * t;
            if (g >= 25) break;

            float dacc[4][4];
#pragma unroll
            for (int qq = 0; qq < 4; qq++)
#pragma unroll
                for (int i = 0; i < 4; i++) dacc[qq][i] = 0.f;

#pragma unroll
            for (int dd4 = 0; dd4 < 8; dd4++) {
                float4 k4[4];
#pragma unroll
                for (int i = 0; i < 4; i++)
                    k4[i] = *(const float4*)&sm.Ks[i * 32 + lane][dd4 * 4];
#pragma unroll
                for (int qq = 0; qq < 4; qq++) {
                    float4 q4 = *(const float4*)&sm.qsm[g * 4 + qq][dd4 * 4];
#pragma unroll
                    for (int i = 0; i < 4; i++)
                        dacc[qq][i] += q4.x*k4[i].x + q4.y*k4[i].y + q4.z*k4[i].z + q4.w*k4[i].w;
                }
            }

            __syncwarp();
#pragma unroll
            for (int qq = 0; qq < 4; qq++) {
                int q = g * 4 + qq;
                const unsigned char* amp = amb + (long)q * HW + c0;
                float sc[4];
#pragma unroll
                for (int i = 0; i < 4; i++) {
                    int s = i * 32 + lane;
                    sc[i] = amp[s] ? dacc[qq][i] * scale : -1e30f;
                }
                float cmax = fmaxf(fmaxf(sc[0], sc[1]), fmaxf(sc[2], sc[3]));
#pragma unroll
                for (int o = 16; o > 0; o >>= 1)
                    cmax = fmaxf(cmax, __shfl_xor_sync(0xffffffffu, cmax, o));
                float nm = fmaxf(m[t][qq], cmax);
                float p[4], ls = 0.f;
#pragma unroll
                for (int i = 0; i < 4; i++) {
                    p[i] = (sc[i] < -1e29f) ? 0.f : __expf(sc[i] - nm);
                    ls += p[i];
                }
#pragma unroll
                for (int o = 16; o > 0; o >>= 1)
                    ls += __shfl_xor_sync(0xffffffffu, ls, o);
                float alpha = __expf(m[t][qq] - nm);
                su[t][qq] = su[t][qq] * alpha + ls;
                oa[t][qq] *= alpha;
                m[t][qq] = nm;
#pragma unroll
                for (int i = 0; i < 4; i++)
                    sm.psm[w][qq][i * 32 + lane] = p[i];
            }
            __syncwarp();

            float po[4] = {0.f, 0.f, 0.f, 0.f};
#pragma unroll
            for (int s4 = 0; s4 < 32; s4++) {
                float v0 = sm.Vs[s4 * 4 + 0][lane];
                float v1 = sm.Vs[s4 * 4 + 1][lane];
                float v2 = sm.Vs[s4 * 4 + 2][lane];
                float v3 = sm.Vs[s4 * 4 + 3][lane];
#pragma unroll
                for (int qq = 0; qq < 4; qq++) {
                    float4 p4 = *(const float4*)&sm.psm[w][qq][s4 * 4];
                    po[qq] += p4.x * v0 + p4.y * v1 + p4.z * v2 + p4.w * v3;
                }
            }
#pragma unroll
            for (int qq = 0; qq < 4; qq++) oa[t][qq] += po[qq];
            __syncwarp();
        }
    }

#pragma unroll
    for (int t = 0; t < 4; t++) {
        int g = w + 8 * t;
        if (g >= 25) break;
#pragma unroll
        for (int qq = 0; qq < 4; qq++)
            O[((long)(b * N_ + g * 4 + qq)) * C_ + h * HD + lane] = oa[t][qq] / su[t][qq];
    }
}

// ============================================================
// LayerNorm over C=256, optional residual
// ============================================================
__global__ void ln_kernel(const float* __restrict__ X, const float* __restrict__ R,
                          const float* __restrict__ g, const float* __restrict__ be,
                          float* __restrict__ Y)
{
    int row = blockIdx.x;
    int t = threadIdx.x;
    float x = X[(long)row * C_ + t];
    if (R) x += R[(long)row * C_ + t];

    __shared__ float red[8];
    float s = x;
#pragma unroll
    for (int o = 16; o > 0; o >>= 1) s += __shfl_xor_sync(0xffffffffu, s, o);
    if ((t & 31) == 0) red[t >> 5] = s;
    __syncthreads();
    if (t < 8) {
        float v = red[t];
#pragma unroll
        for (int o = 4; o > 0; o >>= 1) v += __shfl_xor_sync(0xffu, v, o);
        if (t == 0) red[0] = v;
    }
    __syncthreads();
    float mean = red[0] * (1.f / C_);
    float dv = x - mean;
    float s2 = dv * dv;
    __syncthreads();
#pragma unroll
    for (int o = 16; o > 0; o >>= 1) s2 += __shfl_xor_sync(0xffffffffu, s2, o);
    if ((t & 31) == 0) red[t >> 5] = s2;
    __syncthreads();
    if (t < 8) {
        float v = red[t];
#pragma unroll
        for (int o = 4; o > 0; o >>= 1) v += __shfl_xor_sync(0xffu, v, o);
        if (t == 0) red[0] = v;
    }
    __syncthreads();
    float var = red[0] * (1.f / C_);
    Y[(long)row * C_ + t] = dv * rsqrtf(var + EPSF) * g[t] + be[t];
}

// ============================================================
// host orchestration
// ============================================================
extern "C" void kernel_launch(void* const* d_in, const int* in_sizes, int n_in,
                              void* d_out, int out_size)
{
    (void)in_sizes; (void)n_in; (void)out_size;
    const float* features      = (const float*)d_in[0];
    const float* mask_features = (const float*)d_in[1];
    const float* query_embed   = (const float*)d_in[2];
    const float* Wq  = (const float*)d_in[3];
    const float* bq  = (const float*)d_in[4];
    const float* Wk  = (const float*)d_in[5];
    const float* bk  = (const float*)d_in[6];
    const float* Wv  = (const float*)d_in[7];
    const float* bv  = (const float*)d_in[8];
    const float* Wo  = (const float*)d_in[9];
    const float* bo  = (const float*)d_in[10];
    const float* g1  = (const float*)d_in[11];
    const float* be1 = (const float*)d_in[12];
    const float* W1  = (const float*)d_in[13];
    const float* b1  = (const float*)d_in[14];
    const float* W2  = (const float*)d_in[15];
    const float* b2  = (const float*)d_in[16];
    const float* g2  = (const float*)d_in[17];
    const float* be2 = (const float*)d_in[18];
    const float* gN  = (const float*)d_in[19];
    const float* beN = (const float*)d_in[20];
    const float* Wm1 = (const float*)d_in[21];
    const float* bm1 = (const float*)d_in[22];
    const float* Wm2 = (const float*)d_in[23];
    const float* bm2 = (const float*)d_in[24];
    float* out = (float*)d_out;

    float* S; cudaGetSymbolAddress((void**)&S, g_scratch);
    unsigned char* AM; cudaGetSymbolAddress((void**)&AM, g_am);

    cudaFuncSetAttribute(attn2, cudaFuncAttributeMaxDynamicSharedMemorySize,
                         (int)sizeof(AttnSmem));

    float* Qcur = S + OFF_Q;
    float* E1   = S + OFF_E1;
    float* E    = S + OFF_E;
    float* QB   = S + OFF_QB;
    float* OB   = S + OFF_OB;
    float* TMP  = S + OFF_TMP;
    float* FFH  = S + OFF_FFH;
    float* FE   = S + OFF_FE;
    float* KB   = S + OFF_KB;
    float* VB   = S + OFF_VB;

    const int MQ = B_ * N_;   // 1600 = 25 tiles of 64

    feats_transpose<<<dim3(C_ / 32, HW / 32, B_), dim3(32, 8)>>>(features, FE);
    bcast_queries<<<(B_ * N_ * C_ + 255) / 256, 256>>>(query_embed, Qcur);

    for (int l = 0; l < L_; l++) {
        gemm_bf<<<dim3(4, 25, 1), 128>>>(Qcur, Wm1, bm1, E1, MQ, C_, C_, 1, 0, 0, 0);
        gemm_bf<<<dim3(4, 25, 1), 128>>>(E1, Wm2, bm2, E, MQ, C_, C_, 0, 0, 0, 0);
        float* curp = out + OUT_INTER + (long)l * B_ * N_ * HWM;
        gemm_bf<<<dim3(HWM / 64, 2, B_), 128>>>(E, mask_features, nullptr, curp,
                                                N_, HWM, C_, 0,
                                                (long)N_ * C_, (long)C_ * HWM, (long)N_ * HWM);
        mask_kernel<<<MQ, 1024>>>(curp, AM);

        gemm_bf<<<dim3(4, 25, 1), 128>>>(Qcur, Wq + (long)l * C_ * C_, bq + l * C_,
                                         QB, MQ, C_, C_, 0, 0, 0, 0);
        gemm_bf<<<dim3(4, 256, 1), 128>>>(FE, Wk + (long)l * C_ * C_, bk + l * C_,
                                          KB, B_ * HW, C_, C_, 0, 0, 0, 0);
        gemm_bf<<<dim3(4, 256, 1), 128>>>(FE, Wv + (long)l * C_ * C_, bv + l * C_,
                                          VB, B_ * HW, C_, C_, 0, 0, 0, 0);

        attn2<<<dim3(NH_, B_), 256, sizeof(AttnSmem)>>>(QB, KB, VB, AM, OB);

        gemm_bf<<<dim3(4, 25, 1), 128>>>(OB, Wo + (long)l * C_ * C_, bo + l * C_,
                                         TMP, MQ, C_, C_, 0, 0, 0, 0);
        ln_kernel<<<MQ, C_>>>(Qcur, TMP, g1 + l * C_, be1 + l * C_, Qcur);

        gemm_bf<<<dim3(16, 25, 1), 128>>>(Qcur, W1 + (long)l * C_ * F_, b1 + l * F_,
                                          FFH, MQ, F_, C_, 1, 0, 0, 0);
        gemm_bf<<<dim3(4, 25, 1), 128>>>(FFH, W2 + (long)l * F_ * C_, b2 + l * C_,
                                         TMP, MQ, C_, F_, 0, 0, 0, 0);
        ln_kernel<<<MQ, C_>>>(Qcur, TMP, g2 + l * C_, be2 + l * C_, Qcur);
    }

    ln_kernel<<<MQ, C_>>>(Qcur, nullptr, gN, beN, out + OUT_Q);

    gemm_bf<<<dim3(4, 25, 1), 128>>>(out + OUT_Q, Wm1, bm1, E1, MQ, C_, C_, 1, 0, 0, 0);
    gemm_bf<<<dim3(4, 25, 1), 128>>>(E1, Wm2, bm2, E, MQ, C_, C_, 0, 0, 0, 0);
    gemm_bf<<<dim3(HWM / 64, 2, B_), 128>>>(E, mask_features, nullptr, out + OUT_PRED,
                                            N_, HWM, C_, 0,
                                            (long)N_ * C_, (long)C_ * HWM, (long)N_ * HWM);
}

// round 15
// speedup vs baseline: 1.0458x; 1.0458x over previous
#include <cuda_runtime.h>
#include <cuda_bf16.h>
#include <cstdint>
#include <math.h>

#define B_   16
#define C_   256
#define H_   32
#define W_   32
#define HW   1024
#define HM   128
#define WM   128
#define HWM  16384
#define N_   100
#define F_   1024
#define NH_  8
#define HD   32
#define L_   2
#define EPSF 1e-5f

#define OUT_Q     0
#define OUT_PRED  (B_*N_*C_)
#define OUT_INTER (OUT_PRED + B_*N_*HWM)

#define OFF_Q    0L
#define OFF_E1   409600L
#define OFF_E    819200L
#define OFF_QB   1228800L
#define OFF_OB   1638400L
#define OFF_TMP  2048000L
#define OFF_FFH  2457600L
#define OFF_FE   4096000L
#define OFF_KB   8290304L
#define OFF_VB   12484608L
#define SCRATCH_FLOATS (12484608L + 4194304L)

__device__ float g_scratch[SCRATCH_FLOATS];
__device__ unsigned char g_am[B_ * N_ * HW];

__device__ __forceinline__ uint32_t smem_u32(const void* p) {
    uint32_t a;
    asm("{ .reg .u64 t; cvta.to.shared.u64 t, %1; cvt.u32.u64 %0, t; }" : "=r"(a) : "l"(p));
    return a;
}

__device__ __forceinline__ void ldsm_x4(uint32_t r[4], uint32_t addr) {
    asm volatile("ldmatrix.sync.aligned.m8n8.x4.shared.b16 {%0,%1,%2,%3}, [%4];"
                 : "=r"(r[0]), "=r"(r[1]), "=r"(r[2]), "=r"(r[3]) : "r"(addr));
}

__device__ __forceinline__ void mma_bf16(float c[4], const uint32_t a[4],
                                         uint32_t b0, uint32_t b1) {
    asm volatile(
        "mma.sync.aligned.m16n8k16.row.col.f32.bf16.bf16.f32 "
        "{%0,%1,%2,%3}, {%4,%5,%6,%7}, {%8,%9}, {%0,%1,%2,%3};"
        : "+f"(c[0]), "+f"(c[1]), "+f"(c[2]), "+f"(c[3])
        : "r"(a[0]), "r"(a[1]), "r"(a[2]), "r"(a[3]), "r"(b0), "r"(b1));
}

__device__ __forceinline__ void bf_split_pair(float x0, float x1, uint32_t& hp, uint32_t& lp) {
    __nv_bfloat16 h0 = __float2bfloat16(x0);
    __nv_bfloat16 h1 = __float2bfloat16(x1);
    __nv_bfloat16 l0 = __float2bfloat16(x0 - __bfloat162float(h0));
    __nv_bfloat16 l1 = __float2bfloat16(x1 - __bfloat162float(h1));
    hp = (uint32_t)__bfloat16_as_ushort(h0) | ((uint32_t)__bfloat16_as_ushort(h1) << 16);
    lp = (uint32_t)__bfloat16_as_ushort(l0) | ((uint32_t)__bfloat16_as_ushort(l1) << 16);
}

// ============================================================
// Core bf16 3-split GEMM body (R13-validated):
// Tile 128(M) x 64(N), BK=32; 256 thr / 8 warps, warp tile 32x32.
// 2 CTAs/SM. A [M,K] f32 rm, B [K,N] f32 rm, C = A·B (+bias)(relu).
// N%64==0, K%32==0, M guarded. PAD=40 -> conflict-free ldmatrix.
// ============================================================
#define PAD 40

__device__ __forceinline__ void gemm_core(
    const float* __restrict__ A, const float* __restrict__ B,
    const float* __restrict__ bias, float* __restrict__ C,
    int M, int N, int K, int relu, int m0, int n0,
    __nv_bfloat16* AH, __nv_bfloat16* AL,
    __nv_bfloat16* BH, __nv_bfloat16* BL)
{
    int tid = threadIdx.x, w = tid >> 5, lane = tid & 31;
    int wm = (w & 3) * 32, wn = (w >> 2) * 32;
    int lr = lane >> 2, lc = lane & 3;

    uint32_t ah_b = smem_u32(AH), al_b = smem_u32(AL);
    uint32_t bh_b = smem_u32(BH), bl_b = smem_u32(BL);

    int ar  = tid >> 1, aks = (tid & 1) * 16;
    bool aok = (m0 + ar) < M;
    int bn  = tid & 63, bkh = (tid >> 6) * 8;

    float acc[2][4][4];
#pragma unroll
    for (int mt = 0; mt < 2; mt++)
#pragma unroll
        for (int nt = 0; nt < 4; nt++)
#pragma unroll
            for (int i = 0; i < 4; i++) acc[mt][nt][i] = 0.f;

    float fa[16], fb[8];

    auto load_chunk = [&](int k0) {
        if (aok) {
            const float4* ap = (const float4*)(A + (long)(m0 + ar) * K + k0 + aks);
#pragma unroll
            for (int q = 0; q < 4; q++) { float4 v = ap[q];
                fa[q*4]=v.x; fa[q*4+1]=v.y; fa[q*4+2]=v.z; fa[q*4+3]=v.w; }
        } else {
#pragma unroll
            for (int q = 0; q < 16; q++) fa[q] = 0.f;
        }
#pragma unroll
        for (int j = 0; j < 8; j++)
            fb[j] = B[(long)(k0 + bkh + j) * N + n0 + bn];
    };

    auto store_chunk = [&]() {
        uint32_t hw[8], lw[8];
#pragma unroll
        for (int j = 0; j < 8; j++) bf_split_pair(fa[2*j], fa[2*j+1], hw[j], lw[j]);
        uint32_t* dst = (uint32_t*)&AH[ar * PAD + aks];
        *(uint4*)(dst)     = make_uint4(hw[0], hw[1], hw[2], hw[3]);
        *(uint4*)(dst + 4) = make_uint4(hw[4], hw[5], hw[6], hw[7]);
        dst = (uint32_t*)&AL[ar * PAD + aks];
        *(uint4*)(dst)     = make_uint4(lw[0], lw[1], lw[2], lw[3]);
        *(uint4*)(dst + 4) = make_uint4(lw[4], lw[5], lw[6], lw[7]);
#pragma unroll
        for (int j = 0; j < 4; j++) bf_split_pair(fb[2*j], fb[2*j+1], hw[j], lw[j]);
        *(uint4*)&BH[bn * PAD + bkh] = make_uint4(hw[0], hw[1], hw[2], hw[3]);
        *(uint4*)&BL[bn * PAD + bkh] = make_uint4(lw[0], lw[1], lw[2], lw[3]);
    };

    int NCH = K / 32;
    load_chunk(0);

    for (int t = 0; t < NCH; t++) {
        store_chunk();
        __syncthreads();
        if (t + 1 < NCH) load_chunk((t + 1) * 32);

#pragma unroll
        for (int ks = 0; ks < 32; ks += 16) {
            uint32_t aH[2][4], aL[2][4];
#pragma unroll
            for (int mt = 0; mt < 2; mt++) {
                uint32_t off = (uint32_t)((wm + mt*16 + (lane & 15)) * PAD
                                          + ks + ((lane >> 4) << 3)) * 2;
                ldsm_x4(aH[mt], ah_b + off);
                ldsm_x4(aL[mt], al_b + off);
            }
#pragma unroll
            for (int dt = 0; dt < 2; dt++) {
                uint32_t bh[4], bl[4];
                uint32_t off = (uint32_t)((wn + dt*16 + ((lane >> 4) << 3) + (lane & 7)) * PAD
                                          + ks + (((lane >> 3) & 1) << 3)) * 2;
                ldsm_x4(bh, bh_b + off);
                ldsm_x4(bl, bl_b + off);
#pragma unroll
                for (int s = 0; s < 2; s++) {
                    int nt = dt * 2 + s;
                    uint32_t b0h = bh[2*s], b1h = bh[2*s+1];
                    uint32_t b0l = bl[2*s], b1l = bl[2*s+1];
#pragma unroll
                    for (int mt = 0; mt < 2; mt++) {
                        mma_bf16(acc[mt][nt], aH[mt], b0h, b1h);
                        mma_bf16(acc[mt][nt], aH[mt], b0l, b1l);
                        mma_bf16(acc[mt][nt], aL[mt], b0h, b1h);
                    }
                }
            }
        }
        __syncthreads();
    }

#pragma unroll
    for (int mt = 0; mt < 2; mt++) {
#pragma unroll
        for (int nt = 0; nt < 4; nt++) {
            int row = m0 + wm + mt * 16 + lr;
            int col = n0 + wn + nt * 8 + lc * 2;
            float bx = 0.f, by = 0.f;
            if (bias) { bx = bias[col]; by = bias[col + 1]; }
            float2 v0, v1;
            v0.x = acc[mt][nt][0] + bx; v0.y = acc[mt][nt][1] + by;
            v1.x = acc[mt][nt][2] + bx; v1.y = acc[mt][nt][3] + by;
            if (relu) {
                v0.x = fmaxf(v0.x, 0.f); v0.y = fmaxf(v0.y, 0.f);
                v1.x = fmaxf(v1.x, 0.f); v1.y = fmaxf(v1.y, 0.f);
            }
            if (row < M)     *(float2*)(C + (long)row * N + col)       = v0;
            if (row + 8 < M) *(float2*)(C + (long)(row + 8) * N + col) = v1;
        }
    }
}

__global__ void __launch_bounds__(256, 2)
gemm_bf(const float* __restrict__ A, const float* __restrict__ B,
        const float* __restrict__ bias, float* __restrict__ C,
        int M, int N, int K, int relu, long sA, long sB, long sC)
{
    __shared__ __nv_bfloat16 AH[128 * PAD], AL[128 * PAD];
    __shared__ __nv_bfloat16 BH[64 * PAD],  BL[64 * PAD];
    gemm_core(A + blockIdx.z * sA, B + blockIdx.z * sB, bias, C + blockIdx.z * sC,
              M, N, K, relu, blockIdx.y * 128, blockIdx.x * 64, AH, AL, BH, BL);
}

// dual: z selects (B0,bias0,C0,relu0) or (B1,bias1,C1,relu1); same A.
__global__ void __launch_bounds__(256, 2)
gemm_bf_dual(const float* __restrict__ A,
             const float* __restrict__ B0, const float* __restrict__ bias0,
             float* __restrict__ C0, int relu0,
             const float* __restrict__ B1, const float* __restrict__ bias1,
             float* __restrict__ C1, int relu1,
             int M, int N, int K)
{
    __shared__ __nv_bfloat16 AH[128 * PAD], AL[128 * PAD];
    __shared__ __nv_bfloat16 BH[64 * PAD],  BL[64 * PAD];
    const float* B  = (blockIdx.z == 0) ? B0 : B1;
    const float* bi = (blockIdx.z == 0) ? bias0 : bias1;
    float* C        = (blockIdx.z == 0) ? C0 : C1;
    int relu        = (blockIdx.z == 0) ? relu0 : relu1;
    gemm_core(A, B, bi, C, M, N, K, relu, blockIdx.y * 128, blockIdx.x * 64,
              AH, AL, BH, BL);
}

// ============================================================
// feats transpose: (B, C, HW) -> (B, HW, C)
// ============================================================
__global__ void feats_transpose(const float* __restrict__ feat, float* __restrict__ out)
{
    __shared__ float tile[32][33];
    int b  = blockIdx.z;
    int c0 = blockIdx.x * 32;
    int s0 = blockIdx.y * 32;
    int tx = threadIdx.x, ty = threadIdx.y;
#pragma unroll
    for (int i = 0; i < 32; i += 8)
        tile[ty + i][tx] = feat[((long)b * C_ + c0 + ty + i) * HW + s0 + tx];
    __syncthreads();
#pragma unroll
    for (int i = 0; i < 32; i += 8)
        out[((long)b * HW + s0 + ty + i) * C_ + c0 + tx] = tile[tx][ty + i];
}

__global__ void bcast_queries(const float* __restrict__ qe, float* __restrict__ q)
{
    int i = blockIdx.x * blockDim.x + threadIdx.x;
    if (i < B_ * N_ * C_) q[i] = qe[i % (N_ * C_)];
}

// ============================================================
// attention mask from cur
// ============================================================
__global__ void mask_kernel(const float* __restrict__ cur, unsigned char* __restrict__ am)
{
    int row = blockIdx.x;
    int t = threadIdx.x;
    int y = t >> 5, x = t & 31;
    const float* p = cur + (long)row * HWM;
    int r0 = 4 * y + 1, c0 = 4 * x + 1;
    float v00 = p[r0 * WM + c0],       v01 = p[r0 * WM + c0 + 1];
    float v10 = p[(r0 + 1) * WM + c0], v11 = p[(r0 + 1) * WM + c0 + 1];
    float s = 1.f / (1.f + expf(-v00)) + 1.f / (1.f + expf(-v01))
            + 1.f / (1.f + expf(-v10)) + 1.f / (1.f + expf(-v11));
    int m = (0.25f * s) > 0.5f;

    __shared__ int cnt[32];
    unsigned bal = __ballot_sync(0xffffffffu, m);
    if ((t & 31) == 0) cnt[t >> 5] = __popc(bal);
    __syncthreads();
    if (t < 32) {
        int v = cnt[t];
#pragma unroll
        for (int o = 16; o > 0; o >>= 1) v += __shfl_down_sync(0xffffffffu, v, o);
        if (t == 0) cnt[0] = v;
    }
    __syncthreads();
    am[(long)row * HW + t] = (cnt[0] == 0) ? (unsigned char)1 : (unsigned char)m;
}

// ============================================================
// attention v2 (dynamic smem): block per (h, b); flash-style.
// ============================================================
struct AttnSmem {
    float Ks[128][36];
    float Vs[128][36];
    float qsm[N_][32];
    float psm[8][4][128];
};

extern __shared__ char attn_smem_raw[];

__global__ void __launch_bounds__(256)
attn2(const float* __restrict__ Q, const float* __restrict__ K,
      const float* __restrict__ V, const unsigned char* __restrict__ am,
      float* __restrict__ O)
{
    AttnSmem& sm = *reinterpret_cast<AttnSmem*>(attn_smem_raw);
    int h = blockIdx.x, b = blockIdx.y;

    int tid = threadIdx.x, w = tid >> 5, lane = tid & 31;

    for (int n = w; n < N_; n += 8)
        sm.qsm[n][lane] = Q[((long)(b * N_ + n)) * C_ + h * HD + lane];

    float m[4][4], su[4][4], oa[4][4];
#pragma unroll
    for (int t = 0; t < 4; t++)
#pragma unroll
        for (int qq = 0; qq < 4; qq++) { m[t][qq] = -1e30f; su[t][qq] = 0.f; oa[t][qq] = 0.f; }

    const unsigned char* amb = am + (long)b * N_ * HW;
    const float scale = 0.17677669529663687f;

    for (int c0 = 0; c0 < HW; c0 += 128) {
        __syncthreads();
#pragma unroll
        for (int it = 0; it < 4; it++) {
            int i = tid + it * 256;
            int r = i >> 3, d4 = (i & 7) * 4;
            float4 kv = *(const float4*)(K + ((long)(b * HW + c0 + r)) * C_ + h * HD + d4);
            *(float4*)&sm.Ks[r][d4] = kv;
            float4 vv = *(const float4*)(V + ((long)(b * HW + c0 + r)) * C_ + h * HD + d4);
            *(float4*)&sm.Vs[r][d4] = vv;
        }
        __syncthreads();

#pragma unroll
        for (int t = 0; t < 4; t++) {
            int g = w + 8 * t;
            if (g >= 25) break;

            float dacc[4][4];
#pragma unroll
            for (int qq = 0; qq < 4; qq++)
#pragma unroll
                for (int i = 0; i < 4; i++) dacc[qq][i] = 0.f;

#pragma unroll
            for (int dd4 = 0; dd4 < 8; dd4++) {
                float4 k4[4];
#pragma unroll
                for (int i = 0; i < 4; i++)
                    k4[i] = *(const float4*)&sm.Ks[i * 32 + lane][dd4 * 4];
#pragma unroll
                for (int qq = 0; qq < 4; qq++) {
                    float4 q4 = *(const float4*)&sm.qsm[g * 4 + qq][dd4 * 4];
#pragma unroll
                    for (int i = 0; i < 4; i++)
                        dacc[qq][i] += q4.x*k4[i].x + q4.y*k4[i].y + q4.z*k4[i].z + q4.w*k4[i].w;
                }
            }

            __syncwarp();
#pragma unroll
            for (int qq = 0; qq < 4; qq++) {
                int q = g * 4 + qq;
                const unsigned char* amp = amb + (long)q * HW + c0;
                float sc[4];
#pragma unroll
                for (int i = 0; i < 4; i++) {
                    int s = i * 32 + lane;
                    sc[i] = amp[s] ? dacc[qq][i] * scale : -1e30f;
                }
                float cmax = fmaxf(fmaxf(sc[0], sc[1]), fmaxf(sc[2], sc[3]));
#pragma unroll
                for (int o = 16; o > 0; o >>= 1)
                    cmax = fmaxf(cmax, __shfl_xor_sync(0xffffffffu, cmax, o));
                float nm = fmaxf(m[t][qq], cmax);
                float p[4], ls = 0.f;
#pragma unroll
                for (int i = 0; i < 4; i++) {
                    p[i] = (sc[i] < -1e29f) ? 0.f : __expf(sc[i] - nm);
                    ls += p[i];
                }
#pragma unroll
                for (int o = 16; o > 0; o >>= 1)
                    ls += __shfl_xor_sync(0xffffffffu, ls, o);
                float alpha = __expf(m[t][qq] - nm);
                su[t][qq] = su[t][qq] * alpha + ls;
                oa[t][qq] *= alpha;
                m[t][qq] = nm;
#pragma unroll
                for (int i = 0; i < 4; i++)
                    sm.psm[w][qq][i * 32 + lane] = p[i];
            }
            __syncwarp();

            float po[4] = {0.f, 0.f, 0.f, 0.f};
#pragma unroll
            for (int s4 = 0; s4 < 32; s4++) {
                float v0 = sm.Vs[s4 * 4 + 0][lane];
                float v1 = sm.Vs[s4 * 4 + 1][lane];
                float v2 = sm.Vs[s4 * 4 + 2][lane];
                float v3 = sm.Vs[s4 * 4 + 3][lane];
#pragma unroll
                for (int qq = 0; qq < 4; qq++) {
                    float4 p4 = *(const float4*)&sm.psm[w][qq][s4 * 4];
                    po[qq] += p4.x * v0 + p4.y * v1 + p4.z * v2 + p4.w * v3;
                }
            }
#pragma unroll
            for (int qq = 0; qq < 4; qq++) oa[t][qq] += po[qq];
            __syncwarp();
        }
    }

#pragma unroll
    for (int t = 0; t < 4; t++) {
        int g = w + 8 * t;
        if (g >= 25) break;
#pragma unroll
        for (int qq = 0; qq < 4; qq++)
            O[((long)(b * N_ + g * 4 + qq)) * C_ + h * HD + lane] = oa[t][qq] / su[t][qq];
    }
}

// ============================================================
// LayerNorm over C=256, optional residual
// ============================================================
__global__ void ln_kernel(const float* __restrict__ X, const float* __restrict__ R,
                          const float* __restrict__ g, const float* __restrict__ be,
                          float* __restrict__ Y)
{
    int row = blockIdx.x;
    int t = threadIdx.x;
    float x = X[(long)row * C_ + t];
    if (R) x += R[(long)row * C_ + t];

    __shared__ float red[8];
    float s = x;
#pragma unroll
    for (int o = 16; o > 0; o >>= 1) s += __shfl_xor_sync(0xffffffffu, s, o);
    if ((t & 31) == 0) red[t >> 5] = s;
    __syncthreads();
    if (t < 8) {
        float v = red[t];
#pragma unroll
        for (int o = 4; o > 0; o >>= 1) v += __shfl_xor_sync(0xffu, v, o);
        if (t == 0) red[0] = v;
    }
    __syncthreads();
    float mean = red[0] * (1.f / C_);
    float dv = x - mean;
    float s2 = dv * dv;
    __syncthreads();
#pragma unroll
    for (int o = 16; o > 0; o >>= 1) s2 += __shfl_xor_sync(0xffffffffu, s2, o);
    if ((t & 31) == 0) red[t >> 5] = s2;
    __syncthreads();
    if (t < 8) {
        float v = red[t];
#pragma unroll
        for (int o = 4; o > 0; o >>= 1) v += __shfl_xor_sync(0xffu, v, o);
        if (t == 0) red[0] = v;
    }
    __syncthreads();
    float var = red[0] * (1.f / C_);
    Y[(long)row * C_ + t] = dv * rsqrtf(var + EPSF) * g[t] + be[t];
}

// ============================================================
// host orchestration
// ============================================================
extern "C" void kernel_launch(void* const* d_in, const int* in_sizes, int n_in,
                              void* d_out, int out_size)
{
    (void)in_sizes; (void)n_in; (void)out_size;
    const float* features      = (const float*)d_in[0];
    const float* mask_features = (const float*)d_in[1];
    const float* query_embed   = (const float*)d_in[2];
    const float* Wq  = (const float*)d_in[3];
    const float* bq  = (const float*)d_in[4];
    const float* Wk  = (const float*)d_in[5];
    const float* bk  = (const float*)d_in[6];
    const float* Wv  = (const float*)d_in[7];
    const float* bv  = (const float*)d_in[8];
    const float* Wo  = (const float*)d_in[9];
    const float* bo  = (const float*)d_in[10];
    const float* g1  = (const float*)d_in[11];
    const float* be1 = (const float*)d_in[12];
    const float* W1  = (const float*)d_in[13];
    const float* b1  = (const float*)d_in[14];
    const float* W2  = (const float*)d_in[15];
    const float* b2  = (const float*)d_in[16];
    const float* g2  = (const float*)d_in[17];
    const float* be2 = (const float*)d_in[18];
    const float* gN  = (const float*)d_in[19];
    const float* beN = (const float*)d_in[20];
    const float* Wm1 = (const float*)d_in[21];
    const float* bm1 = (const float*)d_in[22];
    const float* Wm2 = (const float*)d_in[23];
    const float* bm2 = (const float*)d_in[24];
    float* out = (float*)d_out;

    float* S; cudaGetSymbolAddress((void**)&S, g_scratch);
    unsigned char* AM; cudaGetSymbolAddress((void**)&AM, g_am);

    cudaFuncSetAttribute(attn2, cudaFuncAttributeMaxDynamicSharedMemorySize,
                         (int)sizeof(AttnSmem));

    float* Qcur = S + OFF_Q;
    float* E1   = S + OFF_E1;
    float* E    = S + OFF_E;
    float* QB   = S + OFF_QB;
    float* OB   = S + OFF_OB;
    float* TMP  = S + OFF_TMP;
    float* FFH  = S + OFF_FFH;
    float* FE   = S + OFF_FE;
    float* KB   = S + OFF_KB;
    float* VB   = S + OFF_VB;

    const int MQ = B_ * N_;   // 1600, 13 tiles of 128

    feats_transpose<<<dim3(C_ / 32, HW / 32, B_), dim3(32, 8)>>>(features, FE);
    bcast_queries<<<(B_ * N_ * C_ + 255) / 256, 256>>>(query_embed, Qcur);

    for (int l = 0; l < L_; l++) {
        // fused: Wm1->E1 (relu) and Wq->QB, both read Qcur
        gemm_bf_dual<<<dim3(4, 13, 2), 256>>>(Qcur,
                                              Wm1, bm1, E1, 1,
                                              Wq + (long)l * C_ * C_, bq + l * C_, QB, 0,
                                              MQ, C_, C_);
        gemm_bf<<<dim3(4, 13, 1), 256>>>(E1, Wm2, bm2, E, MQ, C_, C_, 0, 0, 0, 0);
        float* curp = out + OUT_INTER + (long)l * B_ * N_ * HWM;
        gemm_bf<<<dim3(HWM / 64, 1, B_), 256>>>(E, mask_features, nullptr, curp,
                                                N_, HWM, C_, 0,
                                                (long)N_ * C_, (long)C_ * HWM, (long)N_ * HWM);
        mask_kernel<<<MQ, 1024>>>(curp, AM);

        // fused: K and V projections, both read FE
        gemm_bf_dual<<<dim3(4, 128, 2), 256>>>(FE,
                                               Wk + (long)l * C_ * C_, bk + l * C_, KB, 0,
                                               Wv + (long)l * C_ * C_, bv + l * C_, VB, 0,
                                               B_ * HW, C_, C_);

        attn2<<<dim3(NH_, B_), 256, sizeof(AttnSmem)>>>(QB, KB, VB, AM, OB);

        gemm_bf<<<dim3(4, 13, 1), 256>>>(OB, Wo + (long)l * C_ * C_, bo + l * C_,
                                         TMP, MQ, C_, C_, 0, 0, 0, 0);
        ln_kernel<<<MQ, C_>>>(Qcur, TMP, g1 + l * C_, be1 + l * C_, Qcur);

        gemm_bf<<<dim3(16, 13, 1), 256>>>(Qcur, W1 + (long)l * C_ * F_, b1 + l * F_,
                                          FFH, MQ, F_, C_, 1, 0, 0, 0);
        gemm_bf<<<dim3(4, 13, 1), 256>>>(FFH, W2 + (long)l * F_ * C_, b2 + l * C_,
                                         TMP, MQ, C_, F_, 0, 0, 0, 0);
        ln_kernel<<<MQ, C_>>>(Qcur, TMP, g2 + l * C_, be2 + l * C_, Qcur);
    }

    ln_kernel<<<MQ, C_>>>(Qcur, nullptr, gN, beN, out + OUT_Q);

    gemm_bf<<<dim3(4, 13, 1), 256>>>(out + OUT_Q, Wm1, bm1, E1, MQ, C_, C_, 1, 0, 0, 0);
    gemm_bf<<<dim3(4, 13, 1), 256>>>(E1, Wm2, bm2, E, MQ, C_, C_, 0, 0, 0, 0);
    gemm_bf<<<dim3(HWM / 64, 1, B_), 256>>>(E, mask_features, nullptr, out + OUT_PRED,
                                            N_, HWM, C_, 0,
                                            (long)N_ * C_, (long)C_ * HWM, (long)N_ * HWM);
}